// round 4
// baseline (speedup 1.0000x reference)
#include <cuda_runtime.h>

#define BB   16
#define CIN  256
#define COUT 256
#define HH   64
#define WW   64
#define HW   (HH*WW)

#define TILE   32       // 32x32 spatial tile per block
#define TCO    16       // couts per block
#define CICHUNK 2       // input channels staged per smem chunk
#define HALO   34       // TILE + 2
#define HPAD   35       // padded row stride (35 mod 32 = 3 -> conflict-free)

// Scratch (no allocations allowed): 256KB + 2.25MB
__device__ float g_scale[COUT * CIN];
__device__ float g_weff[CIN * COUT * 9];   // layout [ci][co][k]

// ---------------------------------------------------------------------------
// scale[o][c] = prod_{j=1..o} relu(weight[j][c]);  scale[0][c] = 1
// ---------------------------------------------------------------------------
__global__ void scale_kernel(const float* __restrict__ weight) {
    int c = threadIdx.x;               // 256 threads, one per input channel
    float s = 1.0f;
    for (int o = 0; o < COUT; ++o) {
        if (o > 0) {
            float w = weight[o * CIN + c];
            s *= (w > 0.0f ? w : 0.0f);
        }
        g_scale[o * CIN + c] = s;
    }
}

// ---------------------------------------------------------------------------
// g_weff[ci][co][k] = conv_w[co][ci][k] * scale[o=co][c=ci]
// ---------------------------------------------------------------------------
__global__ void weff_kernel(const float* __restrict__ conv_w) {
    int idx = blockIdx.x * blockDim.x + threadIdx.x;
    if (idx >= COUT * CIN * 9) return;
    int k  = idx % 9;
    int ci = (idx / 9) % CIN;
    int co = idx / (9 * CIN);
    float v = conv_w[(co * CIN + ci) * 9 + k] * g_scale[co * CIN + ci];
    g_weff[(ci * COUT + co) * 9 + k] = v;
}

// ---------------------------------------------------------------------------
// Direct conv. Block: 256 threads, 32x32 output tile, TCO couts.
// Thread: 4 horizontal pixels x 16 couts = 64 fp32 accumulators.
// ---------------------------------------------------------------------------
__global__ __launch_bounds__(256, 2)
void conv_kernel(const float* __restrict__ in,
                 const float* __restrict__ bias,
                 float* __restrict__ out) {
    __shared__ float s_in[CICHUNK][HALO][HPAD];
    __shared__ float s_w[CICHUNK][TCO][9];

    const int tile = blockIdx.x;                 // 0..3 (2x2 tiles over 64x64)
    const int x0 = (tile & 1) * TILE;
    const int y0 = (tile >> 1) * TILE;
    const int co0 = blockIdx.y * TCO;
    const int b = blockIdx.z;

    const int tid = threadIdx.x;
    const int tx = tid & 7;                      // 0..7 -> strip of 4 pixels
    const int ty = tid >> 3;                     // 0..31

    float acc[TCO][4];
    #pragma unroll
    for (int co = 0; co < TCO; ++co) {
        float bv = bias[co0 + co];
        #pragma unroll
        for (int p = 0; p < 4; ++p) acc[co][p] = bv;
    }

    const float* inb = in + (size_t)b * CIN * HW;

    for (int ci0 = 0; ci0 < CIN; ci0 += CICHUNK) {
        __syncthreads();
        // stage input halo: CICHUNK x 34 x 34
        for (int i = tid; i < CICHUNK * HALO * HALO; i += 256) {
            int cc = i / (HALO * HALO);
            int r  = (i / HALO) % HALO;
            int c  = i % HALO;
            int gy = y0 + r - 1;
            int gx = x0 + c - 1;
            float v = 0.0f;
            if (gy >= 0 && gy < HH && gx >= 0 && gx < WW)
                v = inb[(ci0 + cc) * HW + gy * WW + gx];
            s_in[cc][r][c] = v;
        }
        // stage weights: CICHUNK x TCO x 9 (contiguous in g_weff per ci row)
        for (int i = tid; i < CICHUNK * TCO * 9; i += 256) {
            int cc  = i / (TCO * 9);
            int rem = i % (TCO * 9);
            s_w[cc][rem / 9][rem % 9] =
                g_weff[((ci0 + cc) * COUT + co0) * 9 + rem];
        }
        __syncthreads();

        #pragma unroll
        for (int cc = 0; cc < CICHUNK; ++cc) {
            // 3 rows x 6 cols of input cover this thread's 4-pixel strip
            float iv[3][6];
            #pragma unroll
            for (int dy = 0; dy < 3; ++dy)
                #pragma unroll
                for (int k = 0; k < 6; ++k)
                    iv[dy][k] = s_in[cc][ty + dy][4 * tx + k];

            #pragma unroll
            for (int co = 0; co < TCO; ++co) {
                float w0 = s_w[cc][co][0], w1 = s_w[cc][co][1], w2 = s_w[cc][co][2];
                float w3 = s_w[cc][co][3], w4 = s_w[cc][co][4], w5 = s_w[cc][co][5];
                float w6 = s_w[cc][co][6], w7 = s_w[cc][co][7], w8 = s_w[cc][co][8];
                #pragma unroll
                for (int p = 0; p < 4; ++p) {
                    float v = acc[co][p];
                    v = fmaf(w0, iv[0][p + 0], v);
                    v = fmaf(w1, iv[0][p + 1], v);
                    v = fmaf(w2, iv[0][p + 2], v);
                    v = fmaf(w3, iv[1][p + 0], v);
                    v = fmaf(w4, iv[1][p + 1], v);
                    v = fmaf(w5, iv[1][p + 2], v);
                    v = fmaf(w6, iv[2][p + 0], v);
                    v = fmaf(w7, iv[2][p + 1], v);
                    v = fmaf(w8, iv[2][p + 2], v);
                    acc[co][p] = v;
                }
            }
        }
    }

    // write: 4 consecutive floats per (thread, cout) -> float4 (16B aligned)
    float* ob = out + ((size_t)b * COUT + co0) * HW + (y0 + ty) * WW + x0 + 4 * tx;
    #pragma unroll
    for (int co = 0; co < TCO; ++co) {
        float4 v = make_float4(acc[co][0], acc[co][1], acc[co][2], acc[co][3]);
        *reinterpret_cast<float4*>(ob + co * HW) = v;
    }
}

// ---------------------------------------------------------------------------
extern "C" void kernel_launch(void* const* d_in, const int* in_sizes, int n_in,
                              void* d_out, int out_size) {
    const float* input  = (const float*)d_in[0];   // [16,256,64,64]
    const float* conv_w = (const float*)d_in[1];   // [256,256,3,3]
    const float* conv_b = (const float*)d_in[2];   // [256]
    const float* weight = (const float*)d_in[3];   // [256,256]
    float* out = (float*)d_out;                    // [16,256,64,64]

    scale_kernel<<<1, 256>>>(weight);
    weff_kernel<<<(COUT * CIN * 9 + 255) / 256, 256>>>(conv_w);

    dim3 grid(4, COUT / TCO, BB);                  // 4 x 16 x 16 = 1024 blocks
    conv_kernel<<<grid, 256>>>(input, conv_b, out);
}

// round 12
// speedup vs baseline: 3.6376x; 3.6376x over previous
#include <cuda_runtime.h>
#include <cuda_bf16.h>
#include <cstdint>

#define BBATCH 16
#define CINC  256
#define COUTC 256
#define HH    64
#define WW    64
#define HW    (HH*WW)
#define NCHUNK 36        // 4 ci-groups x 9 taps

// GEMM tiling
#define BM 128           // couts per CTA
#define BN 128           // pixels per CTA (2 rows x 64)
#define BKH 64           // bf16 K elems per chunk (128B rows)

// smem: per stage A_hi|A_lo|B_hi|B_lo each 16KB
#define STAGE 65536
#define A_HI 0
#define A_LO 16384
#define B_HI 32768
#define B_LO 49152
#define SMEM_TOTAL (2*STAGE)     // 131072

// ---------------- device scratch (no allocations allowed) ----------------
__device__ __align__(16) float          g_scale[COUTC * CINC];
__device__ __align__(16) __nv_bfloat16  g_wAh[NCHUNK * 256 * 64];  // [chunk][co][k]
__device__ __align__(16) __nv_bfloat16  g_wAl[NCHUNK * 256 * 64];
__device__ __align__(16) __nv_bfloat16  g_inh[(size_t)BBATCH * HH * WW * CINC]; // NHWC
__device__ __align__(16) __nv_bfloat16  g_inl[(size_t)BBATCH * HH * WW * CINC];

// ---------------- helpers ----------------
__device__ __forceinline__ uint32_t smem_u32(const void* p) {
    uint32_t a;
    asm("{ .reg .u64 t; cvta.to.shared.u64 t, %1; cvt.u32.u64 %0, t; }" : "=r"(a) : "l"(p));
    return a;
}

__device__ __forceinline__ void ldsm4(uint32_t& r0, uint32_t& r1, uint32_t& r2, uint32_t& r3,
                                      uint32_t a) {
    asm volatile("ldmatrix.sync.aligned.m8n8.x4.shared.b16 {%0,%1,%2,%3}, [%4];"
        : "=r"(r0), "=r"(r1), "=r"(r2), "=r"(r3) : "r"(a));
}

__device__ __forceinline__ void mma16816(float* d, const uint32_t* a, const uint32_t* b) {
    asm volatile("mma.sync.aligned.m16n8k16.row.col.f32.bf16.bf16.f32 "
        "{%0,%1,%2,%3}, {%4,%5,%6,%7}, {%8,%9}, {%0,%1,%2,%3};"
        : "+f"(d[0]), "+f"(d[1]), "+f"(d[2]), "+f"(d[3])
        : "r"(a[0]), "r"(a[1]), "r"(a[2]), "r"(a[3]), "r"(b[0]), "r"(b[1]));
}

__device__ __forceinline__ void cpasync16(uint32_t dst, const void* src, int sz) {
    asm volatile("cp.async.cg.shared.global [%0], [%1], 16, %2;"
        :: "r"(dst), "l"(src), "r"(sz));
}
#define CP_COMMIT() asm volatile("cp.async.commit_group;" ::: "memory")
#define CP_WAIT(n)  asm volatile("cp.async.wait_group %0;" :: "n"(n) : "memory")

// ---------------------------------------------------------------------------
// Prep 1: scale[o][c] = prod_{j=1..o} relu(weight[j][c])
// ---------------------------------------------------------------------------
__global__ void scale_kernel(const float* __restrict__ weight) {
    __shared__ float sw[32][257];
    int tid = threadIdx.x;
    float s = 1.0f;
    for (int o0 = 0; o0 < 256; o0 += 32) {
        for (int i = tid; i < 32 * 256; i += 256)
            sw[i >> 8][i & 255] = weight[o0 * 256 + i];
        __syncthreads();
        #pragma unroll
        for (int j = 0; j < 32; ++j) {
            int o = o0 + j;
            float w = sw[j][tid];
            if (o > 0) s *= (w > 0.0f ? w : 0.0f);
            g_scale[o * 256 + tid] = s;
        }
        __syncthreads();
    }
}

// ---------------------------------------------------------------------------
// Prep 2: weights -> bf16 hi/lo, layout [chunk=(ci/64)*9+tap][co][k=ci%64]
// ---------------------------------------------------------------------------
__global__ void wprep_kernel(const float* __restrict__ conv_w) {
    int idx = blockIdx.x * 256 + threadIdx.x;   // < 256*256*9
    int tap = idx % 9;
    int ci  = (idx / 9) % 256;
    int co  = idx / (9 * 256);
    float w = conv_w[idx] * g_scale[co * 256 + ci];
    __nv_bfloat16 h = __float2bfloat16(w);
    __nv_bfloat16 l = __float2bfloat16(w - __bfloat162float(h));
    int chunk = (ci >> 6) * 9 + tap;
    size_t dst = (((size_t)chunk * 256 + co) << 6) + (ci & 63);
    g_wAh[dst] = h;
    g_wAl[dst] = l;
}

// ---------------------------------------------------------------------------
// Prep 3: NCHW fp32 -> NHWC bf16 hi/lo (smem tile transpose)
// ---------------------------------------------------------------------------
__global__ void inprep_kernel(const float* __restrict__ in) {
    __shared__ float t[32][33];
    int tx = threadIdx.x & 31, ty = threadIdx.x >> 5;   // ty 0..7
    int x0  = (blockIdx.x & 1) * 32;
    int ci0 = (blockIdx.x >> 1) * 32;
    int y = blockIdx.y, b = blockIdx.z;
    const float* src = in + (size_t)b * CINC * HW + y * WW;
    #pragma unroll
    for (int j = 0; j < 4; ++j) {
        int ci = ci0 + ty + j * 8;
        t[ty + j * 8][tx] = src[(size_t)ci * HW + x0 + tx];
    }
    __syncthreads();
    #pragma unroll
    for (int j = 0; j < 4; ++j) {
        int x  = x0 + ty + j * 8;
        int ci = ci0 + tx;
        float v = t[tx][ty + j * 8];
        __nv_bfloat16 h = __float2bfloat16(v);
        __nv_bfloat16 l = __float2bfloat16(v - __bfloat162float(h));
        size_t d = (((size_t)(b * 64 + y) * 64) + x) * 256 + ci;
        g_inh[d] = h;
        g_inl[d] = l;
    }
}

// ---------------------------------------------------------------------------
// Main: implicit-GEMM conv via mma.sync (bf16 3-term split, fp32 accum)
// grid (32 ytiles, 16 batch, 2 cotiles), 256 threads, 8 warps (2M x 4N)
// ---------------------------------------------------------------------------
__global__ __launch_bounds__(256, 1)
void conv_mma_kernel(const float* __restrict__ bias, float* __restrict__ out) {
    extern __shared__ char smem[];
    const uint32_t sb = smem_u32(smem);
    const int tid = threadIdx.x;
    const int wid = tid >> 5, l = tid & 31;
    const int warpM = wid >> 2;     // 0..1
    const int warpN = wid & 3;      // 0..3

    const int y0  = blockIdx.x * 2;
    const int b   = blockIdx.y;
    const int co0 = blockIdx.z * BM;

    // ---- lane-constant ldmatrix address parts (XOR-swizzled) ----
    const uint32_t xm = (uint32_t)(l & 7) << 4;
    uint32_t aRow[4];
    #pragma unroll
    for (int mt = 0; mt < 4; ++mt) {
        int m = warpM * 64 + mt * 16 + (l & 7) + ((l >> 3) & 1) * 8;
        aRow[mt] = (uint32_t)m * 128;
    }
    const uint32_t aK = (uint32_t)((l >> 4) & 1) * 16;
    uint32_t bRow[2];
    #pragma unroll
    for (int p = 0; p < 2; ++p) {
        int n = warpN * 32 + p * 16 + ((l >> 4) & 1) * 8 + (l & 7);
        bRow[p] = (uint32_t)n * 128;
    }
    const uint32_t bK = (uint32_t)((l >> 3) & 1) * 16;

    float acc[4][4][4];
    #pragma unroll
    for (int mt = 0; mt < 4; ++mt)
        #pragma unroll
        for (int nt = 0; nt < 4; ++nt)
            #pragma unroll
            for (int q = 0; q < 4; ++q) acc[mt][nt][q] = 0.0f;

    // ---- staging: cp.async one chunk into stage (c&1) ----
    auto prefetch = [&](int c) {
        const uint32_t st = sb + (uint32_t)(c & 1) * STAGE;
        const int cs = c / 9, tap = c - cs * 9;
        const int ky = tap / 3, kx = tap - ky * 3;
        const char* wh = (const char*)(g_wAh + (((size_t)c * 256 + co0) << 6));
        const char* wl = (const char*)(g_wAl + (((size_t)c * 256 + co0) << 6));
        #pragma unroll
        for (int i = 0; i < 4; ++i) {              // A: 128 rows x 128B
            int e = i * 256 + tid;
            int row = e >> 3, slot = e & 7;
            uint32_t d = (uint32_t)row * 128 + (((uint32_t)slot * 16) ^ ((uint32_t)(row & 7) << 4));
            cpasync16(st + A_HI + d, wh + row * 128 + slot * 16, 16);
            cpasync16(st + A_LO + d, wl + row * 128 + slot * 16, 16);
        }
        #pragma unroll
        for (int i = 0; i < 4; ++i) {              // B: 128 pixels x 128B
            int e = i * 256 + tid;
            int pix = e >> 3, slot = e & 7;
            int pr = pix >> 6, px = pix & 63;
            int gy = y0 + pr + ky - 1;
            int gx = px + kx - 1;
            bool v = (gx >= 0) && (gx < WW) && (gy >= 0) && (gy < HH);
            int sz = v ? 16 : 0;
            int cgy = v ? gy : 0, cgx = v ? gx : 0;
            size_t base = (((size_t)(b * 64 + cgy) * 64) + cgx) * 256 + (size_t)cs * 64;
            uint32_t d = (uint32_t)pix * 128 + (((uint32_t)slot * 16) ^ ((uint32_t)(pix & 7) << 4));
            cpasync16(st + B_HI + d, (const char*)(g_inh + base) + slot * 16, sz);
            cpasync16(st + B_LO + d, (const char*)(g_inl + base) + slot * 16, sz);
        }
    };

    prefetch(0);
    CP_COMMIT();

    for (int c = 0; c < NCHUNK; ++c) {
        if (c + 1 < NCHUNK) { prefetch(c + 1); CP_COMMIT(); CP_WAIT(1); }
        else                { CP_WAIT(0); }
        __syncthreads();

        const uint32_t st = sb + (uint32_t)(c & 1) * STAGE;
        #pragma unroll
        for (int ks = 0; ks < 4; ++ks) {
            const uint32_t kb = (uint32_t)ks * 32;
            uint32_t ah[4][4], al[4][4], bh[8], bl[8];
            #pragma unroll
            for (int mt = 0; mt < 4; ++mt) {
                uint32_t ao = aRow[mt] + ((kb + aK) ^ xm);
                ldsm4(ah[mt][0], ah[mt][1], ah[mt][2], ah[mt][3], st + A_HI + ao);
                ldsm4(al[mt][0], al[mt][1], al[mt][2], al[mt][3], st + A_LO + ao);
            }
            #pragma unroll
            for (int p = 0; p < 2; ++p) {
                uint32_t bo = bRow[p] + ((kb + bK) ^ xm);
                ldsm4(bh[p*4+0], bh[p*4+1], bh[p*4+2], bh[p*4+3], st + B_HI + bo);
                ldsm4(bl[p*4+0], bl[p*4+1], bl[p*4+2], bl[p*4+3], st + B_LO + bo);
            }
            #pragma unroll
            for (int mt = 0; mt < 4; ++mt) {
                #pragma unroll
                for (int nt = 0; nt < 4; ++nt) {
                    const uint32_t* bhp = &bh[(nt >> 1) * 4 + (nt & 1) * 2];
                    const uint32_t* blp = &bl[(nt >> 1) * 4 + (nt & 1) * 2];
                    mma16816(acc[mt][nt], ah[mt], bhp);   // hi*hi
                    mma16816(acc[mt][nt], al[mt], bhp);   // lo*hi
                    mma16816(acc[mt][nt], ah[mt], blp);   // hi*lo
                }
            }
        }
        __syncthreads();
    }

    // ---- epilogue: +bias, write NCHW fp32 ----
    #pragma unroll
    for (int mt = 0; mt < 4; ++mt) {
        int r = warpM * 64 + mt * 16 + (l >> 2);
        int co_r = co0 + r;
        float bv0 = bias[co_r];
        float bv1 = bias[co_r + 8];
        float* o0 = out + ((size_t)b * COUTC + co_r) * HW;
        float* o1 = o0 + (size_t)8 * HW;
        #pragma unroll
        for (int nt = 0; nt < 4; ++nt) {
            int n = warpN * 32 + nt * 8 + (l & 3) * 2;
            int y = y0 + (n >> 6), x = n & 63;
            float2 v0 = make_float2(acc[mt][nt][0] + bv0, acc[mt][nt][1] + bv0);
            float2 v1 = make_float2(acc[mt][nt][2] + bv1, acc[mt][nt][3] + bv1);
            *reinterpret_cast<float2*>(o0 + y * WW + x) = v0;
            *reinterpret_cast<float2*>(o1 + y * WW + x) = v1;
        }
    }
}

// ---------------------------------------------------------------------------
extern "C" void kernel_launch(void* const* d_in, const int* in_sizes, int n_in,
                              void* d_out, int out_size) {
    const float* input  = (const float*)d_in[0];   // [16,256,64,64]
    const float* conv_w = (const float*)d_in[1];   // [256,256,3,3]
    const float* conv_b = (const float*)d_in[2];   // [256]
    const float* weight = (const float*)d_in[3];   // [256,256]
    float* out = (float*)d_out;

    cudaFuncSetAttribute(conv_mma_kernel,
                         cudaFuncAttributeMaxDynamicSharedMemorySize, SMEM_TOTAL);

    scale_kernel<<<1, 256>>>(weight);
    wprep_kernel<<<(256 * 256 * 9) / 256, 256>>>(conv_w);
    inprep_kernel<<<dim3(16, 64, 16), 256>>>(input);

    conv_mma_kernel<<<dim3(32, 16, 2), 256, SMEM_TOTAL>>>(conv_b, out);
}

// round 15
// speedup vs baseline: 3.8557x; 1.0600x over previous
#include <cuda_runtime.h>
#include <cuda_bf16.h>
#include <cstdint>

#define BBATCH 16
#define CINC  256
#define COUTC 256
#define HH    64
#define WW    64
#define HW    (HH*WW)
#define NCHUNK 36        // 4 ci-groups x 9 taps

// GEMM tiling
#define BM 128           // couts per CTA
#define BN 128           // pixels per CTA (2 rows x 64)

// smem: per stage A_hi|A_lo|B_hi|B_lo each 16KB
#define STAGE 65536
#define A_HI 0
#define A_LO 16384
#define B_HI 32768
#define B_LO 49152
#define SMEM_TOTAL (2*STAGE)     // 131072

// ---------------- device scratch (no allocations allowed) ----------------
__device__ __align__(16) float          g_scale[COUTC * CINC];
__device__ __align__(16) float          g_segtot[8 * CINC];
__device__ __align__(16) __nv_bfloat16  g_wAh[NCHUNK * 256 * 64];  // [chunk][co][k]
__device__ __align__(16) __nv_bfloat16  g_wAl[NCHUNK * 256 * 64];
__device__ __align__(16) __nv_bfloat16  g_inh[(size_t)BBATCH * HH * WW * CINC]; // NHWC
__device__ __align__(16) __nv_bfloat16  g_inl[(size_t)BBATCH * HH * WW * CINC];

// ---------------- helpers ----------------
__device__ __forceinline__ uint32_t smem_u32(const void* p) {
    uint32_t a;
    asm("{ .reg .u64 t; cvta.to.shared.u64 t, %1; cvt.u32.u64 %0, t; }" : "=r"(a) : "l"(p));
    return a;
}

__device__ __forceinline__ void ldsm4(uint32_t& r0, uint32_t& r1, uint32_t& r2, uint32_t& r3,
                                      uint32_t a) {
    asm volatile("ldmatrix.sync.aligned.m8n8.x4.shared.b16 {%0,%1,%2,%3}, [%4];"
        : "=r"(r0), "=r"(r1), "=r"(r2), "=r"(r3) : "r"(a));
}

__device__ __forceinline__ void mma16816(float* d, const uint32_t* a, const uint32_t* b) {
    asm volatile("mma.sync.aligned.m16n8k16.row.col.f32.bf16.bf16.f32 "
        "{%0,%1,%2,%3}, {%4,%5,%6,%7}, {%8,%9}, {%0,%1,%2,%3};"
        : "+f"(d[0]), "+f"(d[1]), "+f"(d[2]), "+f"(d[3])
        : "r"(a[0]), "r"(a[1]), "r"(a[2]), "r"(a[3]), "r"(b[0]), "r"(b[1]));
}

__device__ __forceinline__ void cpasync16(uint32_t dst, const void* src, int sz) {
    asm volatile("cp.async.cg.shared.global [%0], [%1], 16, %2;"
        :: "r"(dst), "l"(src), "r"(sz));
}
#define CP_COMMIT() asm volatile("cp.async.commit_group;" ::: "memory")
#define CP_WAIT(n)  asm volatile("cp.async.wait_group %0;" :: "n"(n) : "memory")

// ---------------------------------------------------------------------------
// Prep 1a: per-segment cumprod. Block s handles o in [32s, 32s+32).
// ---------------------------------------------------------------------------
__global__ void scale_seg_kernel(const float* __restrict__ weight) {
    int c = threadIdx.x;
    int s = blockIdx.x;
    float p = 1.0f;
    #pragma unroll 8
    for (int j = 0; j < 32; ++j) {
        int o = s * 32 + j;
        if (o > 0) {
            float w = weight[o * 256 + c];
            p *= (w > 0.0f ? w : 0.0f);
        }
        g_scale[o * 256 + c] = p;
    }
    g_segtot[s * 256 + c] = p;
}

// ---------------------------------------------------------------------------
// Prep 1b: multiply each segment's rows by the product of preceding segments.
// ---------------------------------------------------------------------------
__global__ void scale_fix_kernel() {
    int c = threadIdx.x;
    int s = blockIdx.x;          // 0..7
    float p = 1.0f;
    for (int s2 = 0; s2 < s; ++s2) p *= g_segtot[s2 * 256 + c];
    if (s > 0) {
        #pragma unroll 8
        for (int j = 0; j < 32; ++j)
            g_scale[(s * 32 + j) * 256 + c] *= p;
    }
}

// ---------------------------------------------------------------------------
// Prep 2: weights -> bf16 hi/lo, layout [chunk=(ci/64)*9+tap][co][k=ci%64]
// ---------------------------------------------------------------------------
__global__ void wprep_kernel(const float* __restrict__ conv_w) {
    int idx = blockIdx.x * 256 + threadIdx.x;   // < 256*256*9
    int tap = idx % 9;
    int ci  = (idx / 9) % 256;
    int co  = idx / (9 * 256);
    float w = conv_w[idx] * g_scale[co * 256 + ci];
    __nv_bfloat16 h = __float2bfloat16(w);
    __nv_bfloat16 l = __float2bfloat16(w - __bfloat162float(h));
    int chunk = (ci >> 6) * 9 + tap;
    size_t dst = (((size_t)chunk * 256 + co) << 6) + (ci & 63);
    g_wAh[dst] = h;
    g_wAl[dst] = l;
}

// ---------------------------------------------------------------------------
// Prep 3: NCHW fp32 -> NHWC bf16 hi/lo (smem tile transpose)
// ---------------------------------------------------------------------------
__global__ void inprep_kernel(const float* __restrict__ in) {
    __shared__ float t[32][33];
    int tx = threadIdx.x & 31, ty = threadIdx.x >> 5;   // ty 0..7
    int x0  = (blockIdx.x & 1) * 32;
    int ci0 = (blockIdx.x >> 1) * 32;
    int y = blockIdx.y, b = blockIdx.z;
    const float* src = in + (size_t)b * CINC * HW + y * WW;
    #pragma unroll
    for (int j = 0; j < 4; ++j) {
        int ci = ci0 + ty + j * 8;
        t[ty + j * 8][tx] = src[(size_t)ci * HW + x0 + tx];
    }
    __syncthreads();
    #pragma unroll
    for (int j = 0; j < 4; ++j) {
        int x  = x0 + ty + j * 8;
        int ci = ci0 + tx;
        float v = t[tx][ty + j * 8];
        __nv_bfloat16 h = __float2bfloat16(v);
        __nv_bfloat16 l = __float2bfloat16(v - __bfloat162float(h));
        size_t d = (((size_t)(b * 64 + y) * 64) + x) * 256 + ci;
        g_inh[d] = h;
        g_inl[d] = l;
    }
}

// ---------------------------------------------------------------------------
// Main: implicit-GEMM conv via mma.sync (bf16 3-term split, fp32 accum)
// grid (32 ytiles, 16 batch, 2 cotiles), 256 threads, 8 warps (2M x 4N)
// ks-pipelined fragments, term-major MMA issue.
// ---------------------------------------------------------------------------
__global__ __launch_bounds__(256, 1)
void conv_mma_kernel(const float* __restrict__ bias, float* __restrict__ out) {
    extern __shared__ char smem[];
    const uint32_t sb = smem_u32(smem);
    const int tid = threadIdx.x;
    const int wid = tid >> 5, l = tid & 31;
    const int warpM = wid >> 2;     // 0..1
    const int warpN = wid & 3;      // 0..3

    const int y0  = blockIdx.x * 2;
    const int b   = blockIdx.y;
    const int co0 = blockIdx.z * BM;

    // ---- lane-constant ldmatrix address parts (XOR-swizzled) ----
    const uint32_t xm = (uint32_t)(l & 7) << 4;
    uint32_t aRow[4];
    #pragma unroll
    for (int mt = 0; mt < 4; ++mt) {
        int m = warpM * 64 + mt * 16 + (l & 7) + ((l >> 3) & 1) * 8;
        aRow[mt] = (uint32_t)m * 128;
    }
    const uint32_t aK = (uint32_t)((l >> 4) & 1) * 16;
    uint32_t bRow[2];
    #pragma unroll
    for (int p = 0; p < 2; ++p) {
        int n = warpN * 32 + p * 16 + ((l >> 4) & 1) * 8 + (l & 7);
        bRow[p] = (uint32_t)n * 128;
    }
    const uint32_t bK = (uint32_t)((l >> 3) & 1) * 16;

    float acc[4][4][4];
    #pragma unroll
    for (int mt = 0; mt < 4; ++mt)
        #pragma unroll
        for (int nt = 0; nt < 4; ++nt)
            #pragma unroll
            for (int q = 0; q < 4; ++q) acc[mt][nt][q] = 0.0f;

    // ---- staging: cp.async one chunk into stage (c&1) ----
    auto prefetch = [&](int c) {
        const uint32_t st = sb + (uint32_t)(c & 1) * STAGE;
        const int cs = c / 9, tap = c - cs * 9;
        const int ky = tap / 3, kx = tap - ky * 3;
        const char* wh = (const char*)(g_wAh + (((size_t)c * 256 + co0) << 6));
        const char* wl = (const char*)(g_wAl + (((size_t)c * 256 + co0) << 6));
        #pragma unroll
        for (int i = 0; i < 4; ++i) {              // A: 128 rows x 128B
            int e = i * 256 + tid;
            int row = e >> 3, slot = e & 7;
            uint32_t d = (uint32_t)row * 128 + (((uint32_t)slot * 16) ^ ((uint32_t)(row & 7) << 4));
            cpasync16(st + A_HI + d, wh + row * 128 + slot * 16, 16);
            cpasync16(st + A_LO + d, wl + row * 128 + slot * 16, 16);
        }
        #pragma unroll
        for (int i = 0; i < 4; ++i) {              // B: 128 pixels x 128B
            int e = i * 256 + tid;
            int pix = e >> 3, slot = e & 7;
            int pr = pix >> 6, px = pix & 63;
            int gy = y0 + pr + ky - 1;
            int gx = px + kx - 1;
            bool v = (gx >= 0) && (gx < WW) && (gy >= 0) && (gy < HH);
            int sz = v ? 16 : 0;
            int cgy = v ? gy : 0, cgx = v ? gx : 0;
            size_t base = (((size_t)(b * 64 + cgy) * 64) + cgx) * 256 + (size_t)cs * 64;
            uint32_t d = (uint32_t)pix * 128 + (((uint32_t)slot * 16) ^ ((uint32_t)(pix & 7) << 4));
            cpasync16(st + B_HI + d, (const char*)(g_inh + base) + slot * 16, sz);
            cpasync16(st + B_LO + d, (const char*)(g_inl + base) + slot * 16, sz);
        }
    };

    // fragment double buffers (ks pipeline)
    uint32_t ah[2][4][4], al[2][4][4], bh[2][8], bl[2][8];

    prefetch(0);
    CP_COMMIT();

    for (int c = 0; c < NCHUNK; ++c) {
        if (c + 1 < NCHUNK) { prefetch(c + 1); CP_COMMIT(); CP_WAIT(1); }
        else                { CP_WAIT(0); }
        __syncthreads();

        const uint32_t st = sb + (uint32_t)(c & 1) * STAGE;

        // load ks=0 fragments into buffer 0
        {
            const uint32_t kb = 0;
            #pragma unroll
            for (int mt = 0; mt < 4; ++mt) {
                uint32_t ao = aRow[mt] + ((kb + aK) ^ xm);
                ldsm4(ah[0][mt][0], ah[0][mt][1], ah[0][mt][2], ah[0][mt][3], st + A_HI + ao);
                ldsm4(al[0][mt][0], al[0][mt][1], al[0][mt][2], al[0][mt][3], st + A_LO + ao);
            }
            #pragma unroll
            for (int p = 0; p < 2; ++p) {
                uint32_t bo = bRow[p] + ((kb + bK) ^ xm);
                ldsm4(bh[0][p*4+0], bh[0][p*4+1], bh[0][p*4+2], bh[0][p*4+3], st + B_HI + bo);
                ldsm4(bl[0][p*4+0], bl[0][p*4+1], bl[0][p*4+2], bl[0][p*4+3], st + B_LO + bo);
            }
        }

        #pragma unroll
        for (int ks = 0; ks < 4; ++ks) {
            const int cur = ks & 1, nxt = cur ^ 1;
            if (ks < 3) {               // prefetch next k-step's fragments
                const uint32_t kb = (uint32_t)(ks + 1) * 32;
                #pragma unroll
                for (int mt = 0; mt < 4; ++mt) {
                    uint32_t ao = aRow[mt] + ((kb + aK) ^ xm);
                    ldsm4(ah[nxt][mt][0], ah[nxt][mt][1], ah[nxt][mt][2], ah[nxt][mt][3], st + A_HI + ao);
                    ldsm4(al[nxt][mt][0], al[nxt][mt][1], al[nxt][mt][2], al[nxt][mt][3], st + A_LO + ao);
                }
                #pragma unroll
                for (int p = 0; p < 2; ++p) {
                    uint32_t bo = bRow[p] + ((kb + bK) ^ xm);
                    ldsm4(bh[nxt][p*4+0], bh[nxt][p*4+1], bh[nxt][p*4+2], bh[nxt][p*4+3], st + B_HI + bo);
                    ldsm4(bl[nxt][p*4+0], bl[nxt][p*4+1], bl[nxt][p*4+2], bl[nxt][p*4+3], st + B_LO + bo);
                }
            }
            // term-major issue: 16 independent accumulators between acc reuses
            #pragma unroll
            for (int mt = 0; mt < 4; ++mt)
                #pragma unroll
                for (int nt = 0; nt < 4; ++nt)
                    mma16816(acc[mt][nt], ah[cur][mt], &bh[cur][(nt >> 1) * 4 + (nt & 1) * 2]);
            #pragma unroll
            for (int mt = 0; mt < 4; ++mt)
                #pragma unroll
                for (int nt = 0; nt < 4; ++nt)
                    mma16816(acc[mt][nt], al[cur][mt], &bh[cur][(nt >> 1) * 4 + (nt & 1) * 2]);
            #pragma unroll
            for (int mt = 0; mt < 4; ++mt)
                #pragma unroll
                for (int nt = 0; nt < 4; ++nt)
                    mma16816(acc[mt][nt], ah[cur][mt], &bl[cur][(nt >> 1) * 4 + (nt & 1) * 2]);
        }
        __syncthreads();
    }

    // ---- epilogue: +bias, write NCHW fp32 ----
    #pragma unroll
    for (int mt = 0; mt < 4; ++mt) {
        int r = warpM * 64 + mt * 16 + (l >> 2);
        int co_r = co0 + r;
        float bv0 = bias[co_r];
        float bv1 = bias[co_r + 8];
        float* o0 = out + ((size_t)b * COUTC + co_r) * HW;
        float* o1 = o0 + (size_t)8 * HW;
        #pragma unroll
        for (int nt = 0; nt < 4; ++nt) {
            int n = warpN * 32 + nt * 8 + (l & 3) * 2;
            int y = y0 + (n >> 6), x = n & 63;
            float2 v0 = make_float2(acc[mt][nt][0] + bv0, acc[mt][nt][1] + bv0);
            float2 v1 = make_float2(acc[mt][nt][2] + bv1, acc[mt][nt][3] + bv1);
            *reinterpret_cast<float2*>(o0 + y * WW + x) = v0;
            *reinterpret_cast<float2*>(o1 + y * WW + x) = v1;
        }
    }
}

// ---------------------------------------------------------------------------
extern "C" void kernel_launch(void* const* d_in, const int* in_sizes, int n_in,
                              void* d_out, int out_size) {
    const float* input  = (const float*)d_in[0];   // [16,256,64,64]
    const float* conv_w = (const float*)d_in[1];   // [256,256,3,3]
    const float* conv_b = (const float*)d_in[2];   // [256]
    const float* weight = (const float*)d_in[3];   // [256,256]
    float* out = (float*)d_out;

    cudaFuncSetAttribute(conv_mma_kernel,
                         cudaFuncAttributeMaxDynamicSharedMemorySize, SMEM_TOTAL);

    scale_seg_kernel<<<8, 256>>>(weight);
    scale_fix_kernel<<<8, 256>>>();
    wprep_kernel<<<(256 * 256 * 9) / 256, 256>>>(conv_w);
    inprep_kernel<<<dim3(16, 64, 16), 256>>>(input);

    conv_mma_kernel<<<dim3(32, 16, 2), 256, SMEM_TOTAL>>>(conv_b, out);
}